// round 14
// baseline (speedup 1.0000x reference)
#include <cuda_runtime.h>
#include <math.h>

#ifdef expf
#undef expf
#endif
#ifdef logf
#undef logf
#endif

#define E_TOT 1048576
#define NTOT  65536
#define NB    16
#define NPG   4096
#define KC    64
#define DD    128

// d_out layout (float32, flattened reference tuple)
#define OFF_ADJ   131072
#define OFF_LINK  196608
#define OFF_ENT   196609
#define OFF_BATCH 196610
#define OFF_PTR   197634
#define OUT_TOT   197651

// scratch (device globals — no allocation allowed)
__device__ int   g_c[NTOT];
__device__ float g_counts[NB*KC];
__device__ float g_cross[NB];
__device__ float g_asq[NB];
__device__ float g_ent;

// ---------------------------------------------------------------------------
// packed f32x2 helpers (Blackwell FFMA2 — 2x fp32 throughput, PTX-only path)
// ---------------------------------------------------------------------------
__device__ __forceinline__ unsigned long long pk2(float lo, float hi){
    unsigned long long r;
    asm("mov.b64 %0, {%1, %2};" : "=l"(r) : "f"(lo), "f"(hi));
    return r;
}
__device__ __forceinline__ void fma2(unsigned long long& d, unsigned long long a, unsigned long long b){
    asm("fma.rn.f32x2 %0, %1, %2, %0;" : "+l"(d) : "l"(a), "l"(b));
}
__device__ __forceinline__ void unpk2(unsigned long long v, float& lo, float& hi){
    asm("mov.b64 {%0, %1}, %2;" : "=f"(lo), "=f"(hi) : "l"(v));
}
// IEEE add/sub the compiler cannot simplify or contract
__device__ __forceinline__ float add_rn(float a, float b){
    float r; asm("add.rn.f32 %0, %1, %2;" : "=f"(r) : "f"(a), "f"(b)); return r;
}
__device__ __forceinline__ float sub_rn(float a, float b){
    float r; asm("sub.rn.f32 %0, %1, %2;" : "=f"(r) : "f"(a), "f"(b)); return r;
}

// ---------------------------------------------------------------------------
// K0: zero adj + accumulators + constant outputs. 'out' region is NOT zeroed:
// k_pe pool path fully overwrites all 131072 elements.
// ---------------------------------------------------------------------------
__global__ void k_init(float* __restrict__ dout){
    int i = OFF_ADJ + blockIdx.x*256 + threadIdx.x;
    if (i < OFF_LINK) dout[i] = 0.0f;                                   // out_adj
    else if (i >= OFF_BATCH && i < OFF_PTR)  dout[i] = (float)((i-OFF_BATCH) >> 6);
    else if (i >= OFF_PTR   && i < OUT_TOT)  dout[i] = (float)((i-OFF_PTR) << 6);
    int j = i - OUT_TOT;
    if (j >= 0){
        if      (j < NB*KC)        g_counts[j] = 0.0f;
        else if (j < NB*KC+NB)     g_cross[j-NB*KC] = 0.0f;
        else if (j < NB*KC+2*NB)   g_asq[j-NB*KC-NB] = 0.0f;
        else if (j == NB*KC+2*NB)  g_ent = 0.0f;
    }
}

// ---------------------------------------------------------------------------
// K1: logits GEMM (fp32, f32x2-packed) + gumbel argmax + counts + entropy + c[]
// Per-thread FP DAGs frozen (passes at rel_err 9.3474e-4, bit-stable 2 rounds).
// W pairs loaded directly as ulonglong2 (bit-identical to pk2 of adjacent
// floats — removes 16 MOV-packs per g-iteration from the hot loop).
// ---------------------------------------------------------------------------
#define WROW 68   // padded smem row stride for W (17 float4)
#define ZROW 65   // padded smem row stride for zs

// float offsets into dynamic smem
#define SM_XS  0            // [128 n][16 f4] = 8192 floats (row-major, swizzled)
#define SM_WS  8192         // [64][WROW] = 4352 floats (per-chunk W)
#define SM_ZS  0            // ALIAS [128 n][ZROW] = 8320 floats (epilogue)
#define SM_BS  12544        // [64]
#define SM_MXS 12608        // [128]
#define SM_CS  12736        // [128] ints
#define SM_TOT 12864        // floats => 51456 B

__global__ void __launch_bounds__(128, 4)
k_assign(const float* __restrict__ x, const float* __restrict__ W,
         const float* __restrict__ bias, const float* __restrict__ gu)
{
    extern __shared__ float sm[];
    float4* xs4 = (float4*)(sm + SM_XS);
    float*  zs  = sm + SM_ZS;
    float*  Ws  = sm + SM_WS;
    float*  bs  = sm + SM_BS;
    float*  mxs = sm + SM_MXS;
    int*    cs  = (int*)(sm + SM_CS);

    const int t     = threadIdx.x;
    const int node0 = blockIdx.x * 128;
    const int gb    = node0 >> 12;      // graph id (4096 nodes per graph)

    if (t < 64) bs[t] = bias[t];

    const int txk = t & 7, tyn = t >> 3;
    const int k0 = txk << 3, m0 = tyn << 3;
    const int swz = tyn & 3;            // x swizzle for this thread's nodes

    unsigned long long acc[8][4];
    #pragma unroll
    for (int i=0;i<8;i++)
        #pragma unroll
        for (int j=0;j<4;j++) acc[i][j] = 0ULL;

    const float4* x4 = (const float4*)x;
    const float4* W4 = (const float4*)W;
    const float4* Ws4 = (const float4*)Ws;

    // ---- two kd chunks of 64; ascending kd order preserved exactly ----
    #pragma unroll 1
    for (int c = 0; c < 2; c++){
        __syncthreads();   // xs/Ws free (prev chunk consumed)

        // stage W rows [c*64, c*64+64) : 1024 float4
        #pragma unroll
        for (int it = 0; it < 8; it++){
            int f = it*128 + t;
            float4 v = W4[c*1024 + f];
            int kd = f >> 4, kq = (f & 15) << 2;
            float* p = Ws + kd*WROW + kq;
            p[0]=v.x; p[1]=v.y; p[2]=v.z; p[3]=v.w;
        }
        // stage x row-major, swizzled: COALESCED LDG (256B per node)
        #pragma unroll
        for (int it = 0; it < 16; it++){
            int f = it*128 + t;
            int n = f >> 4, q = f & 15;
            float4 v = x4[(size_t)(node0 + n)*32 + c*16 + q];
            xs4[n*16 + (q ^ ((n>>3)&3))] = v;
        }
        __syncthreads();

        #pragma unroll 4
        for (int g = 0; g < 16; g++){
            // this thread's 8 node-float4s for kd group g (conflict-free)
            float4 xv[8];
            #pragma unroll
            for (int i=0;i<8;i++)
                xv[i] = xs4[(m0+i)*16 + (g ^ swz)];
            #pragma unroll
            for (int r = 0; r < 4; r++){         // kd = c*64 + 4g + r, ascending
                const ulonglong2* wp = (const ulonglong2*)(Ws4 + (4*g + r)*17 + 2*txk);
                ulonglong2 rwa = wp[0], rwb = wp[1];   // bits == pk2 of adjacent floats
                #pragma unroll
                for (int i=0;i<8;i++){
                    float xr = (r==0) ? xv[i].x : (r==1) ? xv[i].y :
                               (r==2) ? xv[i].z : xv[i].w;
                    unsigned long long xd = pk2(xr, xr);
                    fma2(acc[i][0], xd, rwa.x);
                    fma2(acc[i][1], xd, rwa.y);
                    fma2(acc[i][2], xd, rwb.x);
                    fma2(acc[i][3], xd, rwb.y);
                }
            }
        }
    }

    // xs/Ws no longer needed; zs reuses the storage
    __syncthreads();

    // ---- per-node: +bias, +gumbel, argmax over 8-lane group; stash z ----
    const float4* u4 = (const float4*)gu;
    #pragma unroll
    for (int i=0;i<8;i++){
        float z[8];
        #pragma unroll
        for (int j=0;j<4;j++){
            float lo, hi; unpk2(acc[i][j], lo, hi);
            z[2*j]   = add_rn(lo, bs[k0 + 2*j]);
            z[2*j+1] = add_rn(hi, bs[k0 + 2*j+1]);
        }
        int node = node0 + m0 + i;
        float4 u0 = u4[(size_t)node*16 + (k0>>2)];
        float4 u1 = u4[(size_t)node*16 + (k0>>2) + 1];
        float uu[8] = {u0.x,u0.y,u0.z,u0.w,u1.x,u1.y,u1.z,u1.w};
        #pragma unroll
        for (int j=0;j<8;j++){
            float g = -(logf)(-(logf)(uu[j]));   // accurate libdevice logf
            z[j] = add_rn(z[j], g);
        }

        // stash exact z for the bit-exact softmax-sum phase
        #pragma unroll
        for (int j=0;j<8;j++) zs[(m0+i)*ZROW + k0 + j] = z[j];

        // local argmax (first-max tie-break, like jnp.argmax)
        float mx = z[0]; int am = k0;
        #pragma unroll
        for (int j=1;j<8;j++) if (z[j] > mx){ mx = z[j]; am = k0+j; }
        // reduce across the 8 lanes holding this node's 64 logits
        #pragma unroll
        for (int off=1; off<8; off<<=1){
            float om = __shfl_xor_sync(0xffffffffu, mx, off);
            int   oa = __shfl_xor_sync(0xffffffffu, am, off);
            if (om > mx || (om == mx && oa < am)){ mx = om; am = oa; }
        }
        if (txk == 0){
            cs[m0+i]  = am;
            mxs[m0+i] = mx;
            atomicAdd(&g_counts[gb*64 + am], 1.0f);
        }
    }
    __syncthreads();
    g_c[node0 + t] = cs[t];

    // ---- phase 2: entropy; SEQUENTIAL ASCENDING softmax denominator ----
    {
        const int lane = t & 31;
        const float* zr = zs + t*ZROW;
        float m  = mxs[t];
        float se = (expf)(sub_rn(zr[0], m));
        #pragma unroll 8
        for (int j = 1; j < 64; j++)
            se = add_rn(se, (expf)(sub_rn(zr[j], m)));
        float ys = __fdiv_rn(1.0f, se);           // y_soft at the argmax
        float sh = sub_rn(add_rn(1.0f, ys), ys);  // straight-through fwd value
        float entloc = -sh * (logf)(sh + 1e-15f);
        #pragma unroll
        for (int off = 16; off; off >>= 1)
            entloc += __shfl_down_sync(0xffffffffu, entloc, off);
        if (lane == 0) atomicAdd(&g_ent, entloc);
    }
}

// ---------------------------------------------------------------------------
// K2: FUSED pool + edges. Both depend only on g_c; running them in ONE grid
// lets edge blocks (ATOMS-bound) and pool blocks (L2-gather-bound) co-run on
// complementary pipes. Blocks 0..511 = edges (launched first: longer pole);
// blocks 512..1535 = pool (one per (b,k)).
// Pool at 512 threads: 16-warp ballot list-build (same ascending list), the
// four accumulator chains a0..a3 (idx = k mod 4) split across 4 thread-groups
// with identical per-chain order; tail into a0 pre-combine; final tree
// (a0+a1)+(a2+a3) unchanged -> byte-identical 'out'.
// ---------------------------------------------------------------------------
#define EPB 2048   // edges per block (32 blocks per graph)
#define FTH 512    // threads per block
#define NEB (E_TOT/EPB)          // 512 edge blocks
#define NPB (NB*KC)              // 1024 pool blocks

__global__ void __launch_bounds__(FTH)
k_pe(const float* __restrict__ x,
     const int* __restrict__ ei, const float* __restrict__ ew,
     float* __restrict__ dout)
{
    __shared__ char smraw[18560];
    const int blk = blockIdx.x;
    const int t   = threadIdx.x;
    const int lane = t & 31, warp = t >> 5;

    if (blk < NEB){
        // ================= EDGES path =================
        float* hist = (float*)smraw;                 // 4096 floats
        float* s_w2 = (float*)(smraw + 16384);       // 16
        float* s_cw = (float*)(smraw + 16448);       // 16
        float* adj  = dout + OFF_ADJ;
        const int b  = blk >> 5;                     // graph id
        const int e0 = blk * EPB;

        float4* h4 = (float4*)hist;
        #pragma unroll
        for (int i = 0; i < KC*KC/4/FTH; i++)
            h4[i*FTH + t] = make_float4(0.f,0.f,0.f,0.f);
        __syncthreads();

        float w2 = 0.0f, cw = 0.0f;
        #pragma unroll
        for (int i = 0; i < EPB/FTH; i++){
            int e = e0 + i*FTH + t;
            int s = ei[e], d = ei[E_TOT + e];
            float w = ew[e];
            int cs_ = g_c[s], cd = g_c[d];
            atomicAdd(&hist[(cs_<<6) + cd], w);
            w2 += w*w;
            if (cs_ == cd) cw += w;
        }

        #pragma unroll
        for (int off=16; off; off>>=1){
            w2 += __shfl_down_sync(0xffffffffu, w2, off);
            cw += __shfl_down_sync(0xffffffffu, cw, off);
        }
        if (lane == 0){ s_w2[warp] = w2; s_cw[warp] = cw; }
        __syncthreads();
        if (t == 0){
            float tw2 = 0.f, tcw = 0.f;
            #pragma unroll
            for (int i=0;i<FTH/32;i++){ tw2 += s_w2[i]; tcw += s_cw[i]; }
            atomicAdd(&g_asq[b],   tw2);
            atomicAdd(&g_cross[b], tcw);
        }

        float* adjb = adj + ((size_t)b << 12);
        #pragma unroll
        for (int i = 0; i < KC*KC/FTH; i++){
            int idx = i*FTH + t;
            float v = hist[idx];
            if (v != 0.0f) atomicAdd(&adjb[idx], v);
        }
    } else {
        // ================= POOL path =================
        int*   list = (int*)smraw;                   // 4096 ints
        int*   wcnt = (int*)(smraw + 16384);         // 16 ints
        float* sp   = (float*)(smraw + 16448);       // 512 floats

        const int p = blk - NEB;                     // 0..1023
        const int b = p >> 6, k = p & 63;
        const int base = b * NPG;

        // list build: 16 warps x 256 nodes, ascending order
        int cv[8];
        #pragma unroll
        for (int i = 0; i < 8; i++)
            cv[i] = g_c[base + warp*256 + i*32 + lane];

        unsigned masks[8];
        int cnt_w = 0;
        #pragma unroll
        for (int i = 0; i < 8; i++){
            unsigned m = __ballot_sync(0xffffffffu, cv[i] == k);
            masks[i] = m;
            cnt_w += __popc(m);
        }
        if (lane == 0) wcnt[warp] = cnt_w;
        __syncthreads();

        int off = 0;
        #pragma unroll
        for (int i = 0; i < 16; i++) if (i < warp) off += wcnt[i];
        #pragma unroll
        for (int i = 0; i < 8; i++){
            unsigned m = masks[i];
            if (cv[i] == k) list[off + __popc(m & ((1u<<lane)-1u))] = warp*256 + i*32 + lane;
            off += __popc(m);
        }
        __syncthreads();

        int M = 0;
        #pragma unroll
        for (int i = 0; i < 16; i++) M += wcnt[i];
        const int M4 = M & ~3;

        // 4 groups own the 4 strided chains (same element order as before)
        const int grp = t >> 7, d = t & 127;
        float a = 0.0f;
        for (int idx = grp; idx < M4; idx += 4)
            a += x[(size_t)(base + list[idx])*128 + d];
        if (grp == 0)
            for (int idx = M4; idx < M; idx++)
                a += x[(size_t)(base + list[idx])*128 + d];
        sp[t] = a;
        __syncthreads();
        if (grp == 0)
            dout[(size_t)p*128 + d] = (sp[d] + sp[128+d]) + (sp[256+d] + sp[384+d]);
    }
}

// ---------------------------------------------------------------------------
// K4: link loss + entropy loss
// ---------------------------------------------------------------------------
__global__ void k_fin(float* __restrict__ dout){
    int t = threadIdx.x;  // 32 threads
    float link = 0.0f;
    if (t < NB){
        float sst = 0.0f;
        #pragma unroll
        for (int k=0;k<KC;k++){ float c = g_counts[t*KC+k]; sst += c*c; }
        float v = g_asq[t] - 2.0f*g_cross[t] + sst;
        link = sqrtf(fmaxf(v, 0.0f)) * (1.0f/65536.0f);   // / e_per
    }
    #pragma unroll
    for (int off=16; off; off>>=1) link += __shfl_down_sync(0xffffffffu, link, off);
    if (t == 0){
        dout[OFF_LINK] = link * (1.0f/16.0f);
        dout[OFF_ENT]  = g_ent * (1.0f/65536.0f);
    }
}

// ---------------------------------------------------------------------------
extern "C" void kernel_launch(void* const* d_in, const int* in_sizes, int n_in,
                              void* d_out, int out_size)
{
    const float* x  = (const float*)d_in[0];
    const float* W  = (const float*)d_in[1];
    const float* b  = (const float*)d_in[2];
    const float* ew = (const float*)d_in[3];
    const float* gu = (const float*)d_in[4];
    const int*   ei = (const int*)d_in[5];
    // d_in[6] = batch_ptr (int64) — graphs are equal-sized, unused
    float* dout = (float*)d_out;

    const int smem = SM_TOT*4;   // 51456 B -> 4 blocks/SM
    cudaFuncSetAttribute(k_assign, cudaFuncAttributeMaxDynamicSharedMemorySize, smem);

    k_init  <<<265, 256>>>(dout);
    k_assign<<<NTOT/128, 128, smem>>>(x, W, b, gu);
    k_pe    <<<NEB + NPB, FTH>>>(x, ei, ew, dout);
    k_fin   <<<1, 32>>>(dout);
}

// round 15
// speedup vs baseline: 1.4903x; 1.4903x over previous
#include <cuda_runtime.h>
#include <math.h>

#ifdef expf
#undef expf
#endif
#ifdef logf
#undef logf
#endif

#define E_TOT 1048576
#define NTOT  65536
#define NB    16
#define NPG   4096
#define KC    64
#define DD    128

// d_out layout (float32, flattened reference tuple)
#define OFF_ADJ   131072
#define OFF_LINK  196608
#define OFF_ENT   196609
#define OFF_BATCH 196610
#define OFF_PTR   197634
#define OUT_TOT   197651

// scratch (device globals — no allocation allowed)
__device__ int   g_c[NTOT];
__device__ float g_counts[NB*KC];
__device__ float g_cross[NB];
__device__ float g_asq[NB];
__device__ float g_ent;

// ---------------------------------------------------------------------------
// packed f32x2 helpers (Blackwell FFMA2 — 2x fp32 throughput, PTX-only path)
// ---------------------------------------------------------------------------
__device__ __forceinline__ unsigned long long pk2(float lo, float hi){
    unsigned long long r;
    asm("mov.b64 %0, {%1, %2};" : "=l"(r) : "f"(lo), "f"(hi));
    return r;
}
__device__ __forceinline__ void fma2(unsigned long long& d, unsigned long long a, unsigned long long b){
    asm("fma.rn.f32x2 %0, %1, %2, %0;" : "+l"(d) : "l"(a), "l"(b));
}
__device__ __forceinline__ void unpk2(unsigned long long v, float& lo, float& hi){
    asm("mov.b64 {%0, %1}, %2;" : "=f"(lo), "=f"(hi) : "l"(v));
}
// IEEE add/sub the compiler cannot simplify or contract
__device__ __forceinline__ float add_rn(float a, float b){
    float r; asm("add.rn.f32 %0, %1, %2;" : "=f"(r) : "f"(a), "f"(b)); return r;
}
__device__ __forceinline__ float sub_rn(float a, float b){
    float r; asm("sub.rn.f32 %0, %1, %2;" : "=f"(r) : "f"(a), "f"(b)); return r;
}

// ---------------------------------------------------------------------------
// K0: zero adj + accumulators + constant outputs. 'out' region is NOT zeroed:
// k_pool fully overwrites all 131072 elements.
// ---------------------------------------------------------------------------
__global__ void k_init(float* __restrict__ dout){
    int i = OFF_ADJ + blockIdx.x*256 + threadIdx.x;
    if (i < OFF_LINK) dout[i] = 0.0f;                                   // out_adj
    else if (i >= OFF_BATCH && i < OFF_PTR)  dout[i] = (float)((i-OFF_BATCH) >> 6);
    else if (i >= OFF_PTR   && i < OUT_TOT)  dout[i] = (float)((i-OFF_PTR) << 6);
    int j = i - OUT_TOT;
    if (j >= 0){
        if      (j < NB*KC)        g_counts[j] = 0.0f;
        else if (j < NB*KC+NB)     g_cross[j-NB*KC] = 0.0f;
        else if (j < NB*KC+2*NB)   g_asq[j-NB*KC-NB] = 0.0f;
        else if (j == NB*KC+2*NB)  g_ent = 0.0f;
    }
}

// ---------------------------------------------------------------------------
// K1: logits GEMM (fp32, f32x2-packed) + gumbel argmax + counts + entropy + c[]
// Per-thread FP DAGs frozen (passes at rel_err 9.3474e-4, bit-stable).
// Structure = R13 (proven 63.7us) + ulonglong2 W loads (bit-identical to pk2
// of adjacent floats; removes 16 MOV-packs per g-iteration).
// ---------------------------------------------------------------------------
#define WROW 68   // padded smem row stride for W (17 float4)
#define ZROW 65   // padded smem row stride for zs

// float offsets into dynamic smem
#define SM_XS  0            // [128 n][16 f4] = 8192 floats (row-major, swizzled)
#define SM_WS  8192         // [64][WROW] = 4352 floats (per-chunk W)
#define SM_ZS  0            // ALIAS [128 n][ZROW] = 8320 floats (epilogue)
#define SM_BS  12544        // [64]
#define SM_MXS 12608        // [128]
#define SM_CS  12736        // [128] ints
#define SM_TOT 12864        // floats => 51456 B

__global__ void __launch_bounds__(128, 4)
k_assign(const float* __restrict__ x, const float* __restrict__ W,
         const float* __restrict__ bias, const float* __restrict__ gu)
{
    extern __shared__ float sm[];
    float4* xs4 = (float4*)(sm + SM_XS);
    float*  zs  = sm + SM_ZS;
    float*  Ws  = sm + SM_WS;
    float*  bs  = sm + SM_BS;
    float*  mxs = sm + SM_MXS;
    int*    cs  = (int*)(sm + SM_CS);

    const int t     = threadIdx.x;
    const int node0 = blockIdx.x * 128;
    const int gb    = node0 >> 12;      // graph id (4096 nodes per graph)

    if (t < 64) bs[t] = bias[t];

    const int txk = t & 7, tyn = t >> 3;
    const int k0 = txk << 3, m0 = tyn << 3;
    const int swz = tyn & 3;            // x swizzle for this thread's nodes

    unsigned long long acc[8][4];
    #pragma unroll
    for (int i=0;i<8;i++)
        #pragma unroll
        for (int j=0;j<4;j++) acc[i][j] = 0ULL;

    const float4* x4 = (const float4*)x;
    const float4* W4 = (const float4*)W;
    const float4* Ws4 = (const float4*)Ws;

    // ---- two kd chunks of 64; ascending kd order preserved exactly ----
    #pragma unroll 1
    for (int c = 0; c < 2; c++){
        __syncthreads();   // xs/Ws free (prev chunk consumed)

        // stage W rows [c*64, c*64+64) : 1024 float4
        #pragma unroll
        for (int it = 0; it < 8; it++){
            int f = it*128 + t;
            float4 v = W4[c*1024 + f];
            int kd = f >> 4, kq = (f & 15) << 2;
            float* p = Ws + kd*WROW + kq;
            p[0]=v.x; p[1]=v.y; p[2]=v.z; p[3]=v.w;
        }
        // stage x row-major, swizzled: COALESCED LDG (256B per node)
        #pragma unroll
        for (int it = 0; it < 16; it++){
            int f = it*128 + t;
            int n = f >> 4, q = f & 15;
            float4 v = x4[(size_t)(node0 + n)*32 + c*16 + q];
            xs4[n*16 + (q ^ ((n>>3)&3))] = v;
        }
        __syncthreads();

        #pragma unroll 4
        for (int g = 0; g < 16; g++){
            // this thread's 8 node-float4s for kd group g (conflict-free)
            float4 xv[8];
            #pragma unroll
            for (int i=0;i<8;i++)
                xv[i] = xs4[(m0+i)*16 + (g ^ swz)];
            #pragma unroll
            for (int r = 0; r < 4; r++){         // kd = c*64 + 4g + r, ascending
                const ulonglong2* wp = (const ulonglong2*)(Ws4 + (4*g + r)*17 + 2*txk);
                ulonglong2 rwa = wp[0], rwb = wp[1];   // bits == pk2 of adjacent floats
                #pragma unroll
                for (int i=0;i<8;i++){
                    float xr = (r==0) ? xv[i].x : (r==1) ? xv[i].y :
                               (r==2) ? xv[i].z : xv[i].w;
                    unsigned long long xd = pk2(xr, xr);
                    fma2(acc[i][0], xd, rwa.x);
                    fma2(acc[i][1], xd, rwa.y);
                    fma2(acc[i][2], xd, rwb.x);
                    fma2(acc[i][3], xd, rwb.y);
                }
            }
        }
    }

    // xs/Ws no longer needed; zs reuses the storage
    __syncthreads();

    // ---- per-node: +bias, +gumbel, argmax over 8-lane group; stash z ----
    const float4* u4 = (const float4*)gu;
    #pragma unroll
    for (int i=0;i<8;i++){
        float z[8];
        #pragma unroll
        for (int j=0;j<4;j++){
            float lo, hi; unpk2(acc[i][j], lo, hi);
            z[2*j]   = add_rn(lo, bs[k0 + 2*j]);
            z[2*j+1] = add_rn(hi, bs[k0 + 2*j+1]);
        }
        int node = node0 + m0 + i;
        float4 u0 = u4[(size_t)node*16 + (k0>>2)];
        float4 u1 = u4[(size_t)node*16 + (k0>>2) + 1];
        float uu[8] = {u0.x,u0.y,u0.z,u0.w,u1.x,u1.y,u1.z,u1.w};
        #pragma unroll
        for (int j=0;j<8;j++){
            float g = -(logf)(-(logf)(uu[j]));   // accurate libdevice logf
            z[j] = add_rn(z[j], g);
        }

        // stash exact z for the bit-exact softmax-sum phase
        #pragma unroll
        for (int j=0;j<8;j++) zs[(m0+i)*ZROW + k0 + j] = z[j];

        // local argmax (first-max tie-break, like jnp.argmax)
        float mx = z[0]; int am = k0;
        #pragma unroll
        for (int j=1;j<8;j++) if (z[j] > mx){ mx = z[j]; am = k0+j; }
        // reduce across the 8 lanes holding this node's 64 logits
        #pragma unroll
        for (int off=1; off<8; off<<=1){
            float om = __shfl_xor_sync(0xffffffffu, mx, off);
            int   oa = __shfl_xor_sync(0xffffffffu, am, off);
            if (om > mx || (om == mx && oa < am)){ mx = om; am = oa; }
        }
        if (txk == 0){
            cs[m0+i]  = am;
            mxs[m0+i] = mx;
            atomicAdd(&g_counts[gb*64 + am], 1.0f);
        }
    }
    __syncthreads();
    g_c[node0 + t] = cs[t];

    // ---- phase 2: entropy; SEQUENTIAL ASCENDING softmax denominator ----
    {
        const int lane = t & 31;
        const float* zr = zs + t*ZROW;
        float m  = mxs[t];
        float se = (expf)(sub_rn(zr[0], m));
        #pragma unroll 8
        for (int j = 1; j < 64; j++)
            se = add_rn(se, (expf)(sub_rn(zr[j], m)));
        float ys = __fdiv_rn(1.0f, se);           // y_soft at the argmax
        float sh = sub_rn(add_rn(1.0f, ys), ys);  // straight-through fwd value
        float entloc = -sh * (logf)(sh + 1e-15f);
        #pragma unroll
        for (int off = 16; off; off >>= 1)
            entloc += __shfl_down_sync(0xffffffffu, entloc, off);
        if (lane == 0) atomicAdd(&g_ent, entloc);
    }
}

// ---------------------------------------------------------------------------
// K2: pooling, out[b,k,:] = sum of x rows with c==k (4-warp parallel list
// build; gather loop order identical -> byte-identical 'out')  [R13 form]
// ---------------------------------------------------------------------------
__global__ void __launch_bounds__(128)
k_pool(const float* __restrict__ x, float* __restrict__ dout)
{
    __shared__ int list[NPG];
    __shared__ int wcnt[4];
    const int blk = blockIdx.x;
    const int b = blk >> 6, k = blk & 63;
    const int base = b * NPG;
    const int t = threadIdx.x;
    const int lane = t & 31, w = t >> 5;

    int cv[32];
    #pragma unroll
    for (int i = 0; i < 32; i++)
        cv[i] = g_c[base + w*1024 + i*32 + lane];

    unsigned masks[32];
    int cnt_w = 0;
    #pragma unroll
    for (int i = 0; i < 32; i++){
        unsigned m = __ballot_sync(0xffffffffu, cv[i] == k);
        masks[i] = m;
        cnt_w += __popc(m);
    }
    if (lane == 0) wcnt[w] = cnt_w;
    __syncthreads();

    int off = 0;
    #pragma unroll
    for (int i = 0; i < 4; i++) if (i < w) off += wcnt[i];
    #pragma unroll
    for (int i = 0; i < 32; i++){
        unsigned m = masks[i];
        if (cv[i] == k) list[off + __popc(m & ((1u<<lane)-1u))] = w*1024 + i*32 + lane;
        off += __popc(m);
    }
    __syncthreads();

    const int M = wcnt[0] + wcnt[1] + wcnt[2] + wcnt[3];
    float a0=0.f, a1=0.f, a2=0.f, a3=0.f;
    int idx = 0;
    for (; idx + 4 <= M; idx += 4){
        a0 += x[(size_t)(base + list[idx  ])*128 + t];
        a1 += x[(size_t)(base + list[idx+1])*128 + t];
        a2 += x[(size_t)(base + list[idx+2])*128 + t];
        a3 += x[(size_t)(base + list[idx+3])*128 + t];
    }
    for (; idx < M; idx++) a0 += x[(size_t)(base + list[idx])*128 + t];
    dout[(size_t)blk*128 + t] = (a0+a1)+(a2+a3);
}

// ---------------------------------------------------------------------------
// K3: edges -> out_adj via SMEM histogram  [R13 proven form]
// ---------------------------------------------------------------------------
#define EPB 2048   // edges per block (32 blocks per graph)
#define ETH 512    // threads per block

__global__ void __launch_bounds__(ETH)
k_edges(const int* __restrict__ ei, const float* __restrict__ ew,
        float* __restrict__ adj)
{
    __shared__ float hist[KC*KC];       // 4096 floats = 16KB
    __shared__ float s_w2[ETH/32], s_cw[ETH/32];

    const int blk = blockIdx.x;         // 512 blocks
    const int b   = blk >> 5;           // graph id (32 blocks per graph)
    const int e0  = blk * EPB;
    const int t   = threadIdx.x;
    const int lane = t & 31, warp = t >> 5;

    // zero histogram
    float4* h4 = (float4*)hist;
    #pragma unroll
    for (int i = 0; i < KC*KC/4/ETH; i++)
        h4[i*ETH + t] = make_float4(0.f,0.f,0.f,0.f);
    __syncthreads();

    float w2 = 0.0f, cw = 0.0f;
    #pragma unroll
    for (int i = 0; i < EPB/ETH; i++){
        int e = e0 + i*ETH + t;
        int s = ei[e], d = ei[E_TOT + e];
        float w = ew[e];
        int cs_ = g_c[s], cd = g_c[d];   // L1-resident (16KB/graph window)
        atomicAdd(&hist[(cs_<<6) + cd], w);
        w2 += w*w;
        if (cs_ == cd) cw += w;
    }

    // block-reduce w2 / cw
    #pragma unroll
    for (int off=16; off; off>>=1){
        w2 += __shfl_down_sync(0xffffffffu, w2, off);
        cw += __shfl_down_sync(0xffffffffu, cw, off);
    }
    if (lane == 0){ s_w2[warp] = w2; s_cw[warp] = cw; }
    __syncthreads();
    if (t == 0){
        float tw2 = 0.f, tcw = 0.f;
        #pragma unroll
        for (int i=0;i<ETH/32;i++){ tw2 += s_w2[i]; tcw += s_cw[i]; }
        atomicAdd(&g_asq[b],   tw2);
        atomicAdd(&g_cross[b], tcw);
    }

    // merge histogram into adj (coalesced REDG; skip empty bins)
    float* adjb = adj + ((size_t)b << 12);
    #pragma unroll
    for (int i = 0; i < KC*KC/ETH; i++){
        int idx = i*ETH + t;
        float v = hist[idx];
        if (v != 0.0f) atomicAdd(&adjb[idx], v);
    }
}

// ---------------------------------------------------------------------------
// K4: link loss + entropy loss
// ---------------------------------------------------------------------------
__global__ void k_fin(float* __restrict__ dout){
    int t = threadIdx.x;  // 32 threads
    float link = 0.0f;
    if (t < NB){
        float sst = 0.0f;
        #pragma unroll
        for (int k=0;k<KC;k++){ float c = g_counts[t*KC+k]; sst += c*c; }
        float v = g_asq[t] - 2.0f*g_cross[t] + sst;
        link = sqrtf(fmaxf(v, 0.0f)) * (1.0f/65536.0f);   // / e_per
    }
    #pragma unroll
    for (int off=16; off; off>>=1) link += __shfl_down_sync(0xffffffffu, link, off);
    if (t == 0){
        dout[OFF_LINK] = link * (1.0f/16.0f);
        dout[OFF_ENT]  = g_ent * (1.0f/65536.0f);
    }
}

// ---------------------------------------------------------------------------
extern "C" void kernel_launch(void* const* d_in, const int* in_sizes, int n_in,
                              void* d_out, int out_size)
{
    const float* x  = (const float*)d_in[0];
    const float* W  = (const float*)d_in[1];
    const float* b  = (const float*)d_in[2];
    const float* ew = (const float*)d_in[3];
    const float* gu = (const float*)d_in[4];
    const int*   ei = (const int*)d_in[5];
    // d_in[6] = batch_ptr (int64) — graphs are equal-sized, unused
    float* dout = (float*)d_out;

    const int smem = SM_TOT*4;   // 51456 B -> 4 blocks/SM
    cudaFuncSetAttribute(k_assign, cudaFuncAttributeMaxDynamicSharedMemorySize, smem);

    k_init  <<<265, 256>>>(dout);
    k_assign<<<NTOT/128, 128, smem>>>(x, W, b, gu);
    k_pool  <<<NB*KC, 128>>>(x, dout);
    k_edges <<<E_TOT/EPB, ETH>>>(ei, ew, dout + OFF_ADJ);
    k_fin   <<<1, 32>>>(dout);
}

// round 16
// speedup vs baseline: 1.5174x; 1.0182x over previous
#include <cuda_runtime.h>
#include <math.h>

#ifdef expf
#undef expf
#endif
#ifdef logf
#undef logf
#endif

#define E_TOT 1048576
#define NTOT  65536
#define NB    16
#define NPG   4096
#define KC    64
#define DD    128

// d_out layout (float32, flattened reference tuple)
#define OFF_ADJ   131072
#define OFF_LINK  196608
#define OFF_ENT   196609
#define OFF_BATCH 196610
#define OFF_PTR   197634
#define OUT_TOT   197651

// scratch (device globals — no allocation allowed)
__device__ int   g_c[NTOT];
__device__ float g_counts[NB*KC];
__device__ float g_cross[NB];
__device__ float g_asq[NB];
__device__ float g_ent;

// ---------------------------------------------------------------------------
// packed f32x2 helpers (Blackwell FFMA2 — 2x fp32 throughput, PTX-only path)
// ---------------------------------------------------------------------------
__device__ __forceinline__ unsigned long long pk2(float lo, float hi){
    unsigned long long r;
    asm("mov.b64 %0, {%1, %2};" : "=l"(r) : "f"(lo), "f"(hi));
    return r;
}
__device__ __forceinline__ void fma2(unsigned long long& d, unsigned long long a, unsigned long long b){
    asm("fma.rn.f32x2 %0, %1, %2, %0;" : "+l"(d) : "l"(a), "l"(b));
}
__device__ __forceinline__ void unpk2(unsigned long long v, float& lo, float& hi){
    asm("mov.b64 {%0, %1}, %2;" : "=f"(lo), "=f"(hi) : "l"(v));
}
// IEEE add/sub the compiler cannot simplify or contract
__device__ __forceinline__ float add_rn(float a, float b){
    float r; asm("add.rn.f32 %0, %1, %2;" : "=f"(r) : "f"(a), "f"(b)); return r;
}
__device__ __forceinline__ float sub_rn(float a, float b){
    float r; asm("sub.rn.f32 %0, %1, %2;" : "=f"(r) : "f"(a), "f"(b)); return r;
}

// ---------------------------------------------------------------------------
// K0: zero adj + accumulators + constant outputs. 'out' region is NOT zeroed:
// k_pool fully overwrites all 131072 elements.
// ---------------------------------------------------------------------------
__global__ void k_init(float* __restrict__ dout){
    int i = OFF_ADJ + blockIdx.x*256 + threadIdx.x;
    if (i < OFF_LINK) dout[i] = 0.0f;                                   // out_adj
    else if (i >= OFF_BATCH && i < OFF_PTR)  dout[i] = (float)((i-OFF_BATCH) >> 6);
    else if (i >= OFF_PTR   && i < OUT_TOT)  dout[i] = (float)((i-OFF_PTR) << 6);
    int j = i - OUT_TOT;
    if (j >= 0){
        if      (j < NB*KC)        g_counts[j] = 0.0f;
        else if (j < NB*KC+NB)     g_cross[j-NB*KC] = 0.0f;
        else if (j < NB*KC+2*NB)   g_asq[j-NB*KC-NB] = 0.0f;
        else if (j == NB*KC+2*NB)  g_ent = 0.0f;
    }
}

// ---------------------------------------------------------------------------
// K1: logits GEMM (fp32, f32x2-packed) + gumbel argmax + counts + entropy + c[]
// EXACT R13 form (proven 63.7us, rel_err bit-stable at 9.3474e-4).
// ---------------------------------------------------------------------------
#define WROW 68   // padded smem row stride for W (17 float4)
#define ZROW 65   // padded smem row stride for zs

// float offsets into dynamic smem
#define SM_XS  0            // [128 n][16 f4] = 8192 floats (row-major, swizzled)
#define SM_WS  8192         // [64][WROW] = 4352 floats (per-chunk W)
#define SM_ZS  0            // ALIAS [128 n][ZROW] = 8320 floats (epilogue)
#define SM_BS  12544        // [64]
#define SM_MXS 12608        // [128]
#define SM_CS  12736        // [128] ints
#define SM_TOT 12864        // floats => 51456 B

__global__ void __launch_bounds__(128, 4)
k_assign(const float* __restrict__ x, const float* __restrict__ W,
         const float* __restrict__ bias, const float* __restrict__ gu)
{
    extern __shared__ float sm[];
    float4* xs4 = (float4*)(sm + SM_XS);
    float*  zs  = sm + SM_ZS;
    float*  Ws  = sm + SM_WS;
    float*  bs  = sm + SM_BS;
    float*  mxs = sm + SM_MXS;
    int*    cs  = (int*)(sm + SM_CS);

    const int t     = threadIdx.x;
    const int node0 = blockIdx.x * 128;
    const int gb    = node0 >> 12;      // graph id (4096 nodes per graph)

    if (t < 64) bs[t] = bias[t];

    const int txk = t & 7, tyn = t >> 3;
    const int k0 = txk << 3, m0 = tyn << 3;
    const int swz = tyn & 3;            // x swizzle for this thread's nodes

    unsigned long long acc[8][4];
    #pragma unroll
    for (int i=0;i<8;i++)
        #pragma unroll
        for (int j=0;j<4;j++) acc[i][j] = 0ULL;

    const float4* x4 = (const float4*)x;
    const float4* W4 = (const float4*)W;
    const float4* Ws4 = (const float4*)Ws;

    // ---- two kd chunks of 64; ascending kd order preserved exactly ----
    #pragma unroll 1
    for (int c = 0; c < 2; c++){
        __syncthreads();   // xs/Ws free (prev chunk consumed)

        // stage W rows [c*64, c*64+64) : 1024 float4
        #pragma unroll
        for (int it = 0; it < 8; it++){
            int f = it*128 + t;
            float4 v = W4[c*1024 + f];
            int kd = f >> 4, kq = (f & 15) << 2;
            float* p = Ws + kd*WROW + kq;
            p[0]=v.x; p[1]=v.y; p[2]=v.z; p[3]=v.w;
        }
        // stage x row-major, swizzled: COALESCED LDG (256B per node)
        #pragma unroll
        for (int it = 0; it < 16; it++){
            int f = it*128 + t;
            int n = f >> 4, q = f & 15;
            float4 v = x4[(size_t)(node0 + n)*32 + c*16 + q];
            xs4[n*16 + (q ^ ((n>>3)&3))] = v;
        }
        __syncthreads();

        #pragma unroll 4
        for (int g = 0; g < 16; g++){
            // this thread's 8 node-float4s for kd group g (conflict-free)
            float4 xv[8];
            #pragma unroll
            for (int i=0;i<8;i++)
                xv[i] = xs4[(m0+i)*16 + (g ^ swz)];
            #pragma unroll
            for (int r = 0; r < 4; r++){         // kd = c*64 + 4g + r, ascending
                const float4* wp = Ws4 + (4*g + r)*17 + 2*txk;
                float4 w0 = wp[0], w1 = wp[1];
                unsigned long long rw0 = pk2(w0.x,w0.y), rw1 = pk2(w0.z,w0.w);
                unsigned long long rw2 = pk2(w1.x,w1.y), rw3 = pk2(w1.z,w1.w);
                #pragma unroll
                for (int i=0;i<8;i++){
                    float xr = (r==0) ? xv[i].x : (r==1) ? xv[i].y :
                               (r==2) ? xv[i].z : xv[i].w;
                    unsigned long long xd = pk2(xr, xr);
                    fma2(acc[i][0], xd, rw0);
                    fma2(acc[i][1], xd, rw1);
                    fma2(acc[i][2], xd, rw2);
                    fma2(acc[i][3], xd, rw3);
                }
            }
        }
    }

    // xs/Ws no longer needed; zs reuses the storage
    __syncthreads();

    // ---- per-node: +bias, +gumbel, argmax over 8-lane group; stash z ----
    const float4* u4 = (const float4*)gu;
    #pragma unroll
    for (int i=0;i<8;i++){
        float z[8];
        #pragma unroll
        for (int j=0;j<4;j++){
            float lo, hi; unpk2(acc[i][j], lo, hi);
            z[2*j]   = add_rn(lo, bs[k0 + 2*j]);
            z[2*j+1] = add_rn(hi, bs[k0 + 2*j+1]);
        }
        int node = node0 + m0 + i;
        float4 u0 = u4[(size_t)node*16 + (k0>>2)];
        float4 u1 = u4[(size_t)node*16 + (k0>>2) + 1];
        float uu[8] = {u0.x,u0.y,u0.z,u0.w,u1.x,u1.y,u1.z,u1.w};
        #pragma unroll
        for (int j=0;j<8;j++){
            float g = -(logf)(-(logf)(uu[j]));   // accurate libdevice logf
            z[j] = add_rn(z[j], g);
        }

        // stash exact z for the bit-exact softmax-sum phase
        #pragma unroll
        for (int j=0;j<8;j++) zs[(m0+i)*ZROW + k0 + j] = z[j];

        // local argmax (first-max tie-break, like jnp.argmax)
        float mx = z[0]; int am = k0;
        #pragma unroll
        for (int j=1;j<8;j++) if (z[j] > mx){ mx = z[j]; am = k0+j; }
        // reduce across the 8 lanes holding this node's 64 logits
        #pragma unroll
        for (int off=1; off<8; off<<=1){
            float om = __shfl_xor_sync(0xffffffffu, mx, off);
            int   oa = __shfl_xor_sync(0xffffffffu, am, off);
            if (om > mx || (om == mx && oa < am)){ mx = om; am = oa; }
        }
        if (txk == 0){
            cs[m0+i]  = am;
            mxs[m0+i] = mx;
            atomicAdd(&g_counts[gb*64 + am], 1.0f);
        }
    }
    __syncthreads();
    g_c[node0 + t] = cs[t];

    // ---- phase 2: entropy; SEQUENTIAL ASCENDING softmax denominator ----
    {
        const int lane = t & 31;
        const float* zr = zs + t*ZROW;
        float m  = mxs[t];
        float se = (expf)(sub_rn(zr[0], m));
        #pragma unroll 8
        for (int j = 1; j < 64; j++)
            se = add_rn(se, (expf)(sub_rn(zr[j], m)));
        float ys = __fdiv_rn(1.0f, se);           // y_soft at the argmax
        float sh = sub_rn(add_rn(1.0f, ys), ys);  // straight-through fwd value
        float entloc = -sh * (logf)(sh + 1e-15f);
        #pragma unroll
        for (int off = 16; off; off >>= 1)
            entloc += __shfl_down_sync(0xffffffffu, entloc, off);
        if (lane == 0) atomicAdd(&g_ent, entloc);
    }
}

// ---------------------------------------------------------------------------
// K2: pooling, out[b,k,:] = sum of x rows with c==k.
// 256 threads: 8-warp ballot list build (same ascending list); accumulator
// chains split across 2 groups — group0 owns a0,a1 (idx = 0,1 mod 4, tail
// into a0), group1 owns a2,a3. Per-chain add order and final tree
// (a0+a1)+(a2+a3) preserved exactly -> byte-identical 'out'.
// ---------------------------------------------------------------------------
__global__ void __launch_bounds__(256)
k_pool(const float* __restrict__ x, float* __restrict__ dout)
{
    __shared__ int   list[NPG];
    __shared__ int   wcnt[8];
    __shared__ float sp[256];
    const int blk = blockIdx.x;
    const int b = blk >> 6, k = blk & 63;
    const int base = b * NPG;
    const int t = threadIdx.x;
    const int lane = t & 31, w = t >> 5;    // 8 warps

    int cv[16];
    #pragma unroll
    for (int i = 0; i < 16; i++)
        cv[i] = g_c[base + w*512 + i*32 + lane];

    unsigned masks[16];
    int cnt_w = 0;
    #pragma unroll
    for (int i = 0; i < 16; i++){
        unsigned m = __ballot_sync(0xffffffffu, cv[i] == k);
        masks[i] = m;
        cnt_w += __popc(m);
    }
    if (lane == 0) wcnt[w] = cnt_w;
    __syncthreads();

    int off = 0;
    #pragma unroll
    for (int i = 0; i < 8; i++) if (i < w) off += wcnt[i];
    #pragma unroll
    for (int i = 0; i < 16; i++){
        unsigned m = masks[i];
        if (cv[i] == k) list[off + __popc(m & ((1u<<lane)-1u))] = w*512 + i*32 + lane;
        off += __popc(m);
    }
    __syncthreads();

    int M = 0;
    #pragma unroll
    for (int i = 0; i < 8; i++) M += wcnt[i];
    const int M4 = M & ~3;

    const int grp = t >> 7, d = t & 127;
    // group g owns chains 2g (aA) and 2g+1 (aB); same per-chain ascending order
    float aA = 0.0f, aB = 0.0f;
    for (int idx = 2*grp;     idx < M4; idx += 4)
        aA += x[(size_t)(base + list[idx])*128 + d];
    for (int idx = 2*grp + 1; idx < M4; idx += 4)
        aB += x[(size_t)(base + list[idx])*128 + d];
    if (grp == 0)
        for (int idx = M4; idx < M; idx++)       // tail into a0, ascending
            aA += x[(size_t)(base + list[idx])*128 + d];
    sp[t] = aA + aB;                              // (a0+a1) / (a2+a3)
    __syncthreads();
    if (grp == 0)
        dout[(size_t)blk*128 + d] = sp[d] + sp[128 + d];   // (a0+a1)+(a2+a3)
}

// ---------------------------------------------------------------------------
// K3: edges -> out_adj via SMEM histogram  [R13 proven form]
// ---------------------------------------------------------------------------
#define EPB 2048   // edges per block (32 blocks per graph)
#define ETH 512    // threads per block

__global__ void __launch_bounds__(ETH)
k_edges(const int* __restrict__ ei, const float* __restrict__ ew,
        float* __restrict__ adj)
{
    __shared__ float hist[KC*KC];       // 4096 floats = 16KB
    __shared__ float s_w2[ETH/32], s_cw[ETH/32];

    const int blk = blockIdx.x;         // 512 blocks
    const int b   = blk >> 5;           // graph id (32 blocks per graph)
    const int e0  = blk * EPB;
    const int t   = threadIdx.x;
    const int lane = t & 31, warp = t >> 5;

    // zero histogram
    float4* h4 = (float4*)hist;
    #pragma unroll
    for (int i = 0; i < KC*KC/4/ETH; i++)
        h4[i*ETH + t] = make_float4(0.f,0.f,0.f,0.f);
    __syncthreads();

    float w2 = 0.0f, cw = 0.0f;
    #pragma unroll
    for (int i = 0; i < EPB/ETH; i++){
        int e = e0 + i*ETH + t;
        int s = ei[e], d = ei[E_TOT + e];
        float w = ew[e];
        int cs_ = g_c[s], cd = g_c[d];   // L1-resident (16KB/graph window)
        atomicAdd(&hist[(cs_<<6) + cd], w);
        w2 += w*w;
        if (cs_ == cd) cw += w;
    }

    // block-reduce w2 / cw
    #pragma unroll
    for (int off=16; off; off>>=1){
        w2 += __shfl_down_sync(0xffffffffu, w2, off);
        cw += __shfl_down_sync(0xffffffffu, cw, off);
    }
    if (lane == 0){ s_w2[warp] = w2; s_cw[warp] = cw; }
    __syncthreads();
    if (t == 0){
        float tw2 = 0.f, tcw = 0.f;
        #pragma unroll
        for (int i=0;i<ETH/32;i++){ tw2 += s_w2[i]; tcw += s_cw[i]; }
        atomicAdd(&g_asq[b],   tw2);
        atomicAdd(&g_cross[b], tcw);
    }

    // merge histogram into adj (coalesced REDG; skip empty bins)
    float* adjb = adj + ((size_t)b << 12);
    #pragma unroll
    for (int i = 0; i < KC*KC/ETH; i++){
        int idx = i*ETH + t;
        float v = hist[idx];
        if (v != 0.0f) atomicAdd(&adjb[idx], v);
    }
}

// ---------------------------------------------------------------------------
// K4: link loss + entropy loss
// ---------------------------------------------------------------------------
__global__ void k_fin(float* __restrict__ dout){
    int t = threadIdx.x;  // 32 threads
    float link = 0.0f;
    if (t < NB){
        float sst = 0.0f;
        #pragma unroll
        for (int k=0;k<KC;k++){ float c = g_counts[t*KC+k]; sst += c*c; }
        float v = g_asq[t] - 2.0f*g_cross[t] + sst;
        link = sqrtf(fmaxf(v, 0.0f)) * (1.0f/65536.0f);   // / e_per
    }
    #pragma unroll
    for (int off=16; off; off>>=1) link += __shfl_down_sync(0xffffffffu, link, off);
    if (t == 0){
        dout[OFF_LINK] = link * (1.0f/16.0f);
        dout[OFF_ENT]  = g_ent * (1.0f/65536.0f);
    }
}

// ---------------------------------------------------------------------------
extern "C" void kernel_launch(void* const* d_in, const int* in_sizes, int n_in,
                              void* d_out, int out_size)
{
    const float* x  = (const float*)d_in[0];
    const float* W  = (const float*)d_in[1];
    const float* b  = (const float*)d_in[2];
    const float* ew = (const float*)d_in[3];
    const float* gu = (const float*)d_in[4];
    const int*   ei = (const int*)d_in[5];
    // d_in[6] = batch_ptr (int64) — graphs are equal-sized, unused
    float* dout = (float*)d_out;

    const int smem = SM_TOT*4;   // 51456 B -> 4 blocks/SM
    cudaFuncSetAttribute(k_assign, cudaFuncAttributeMaxDynamicSharedMemorySize, smem);

    k_init  <<<265, 256>>>(dout);
    k_assign<<<NTOT/128, 128, smem>>>(x, W, b, gu);
    k_pool  <<<NB*KC, 256>>>(x, dout);
    k_edges <<<E_TOT/EPB, ETH>>>(ei, ew, dout + OFF_ADJ);
    k_fin   <<<1, 32>>>(dout);
}

// round 17
// speedup vs baseline: 1.6042x; 1.0571x over previous
#include <cuda_runtime.h>
#include <math.h>

#ifdef expf
#undef expf
#endif
#ifdef logf
#undef logf
#endif

#define E_TOT 1048576
#define NTOT  65536
#define NB    16
#define NPG   4096
#define KC    64
#define DD    128

// d_out layout (float32, flattened reference tuple)
#define OFF_ADJ   131072
#define OFF_LINK  196608
#define OFF_ENT   196609
#define OFF_BATCH 196610
#define OFF_PTR   197634
#define OUT_TOT   197651

// scratch (device globals — no allocation allowed)
__device__ int   g_c[NTOT];
__device__ float g_counts[NB*KC];
__device__ float g_cross[NB];
__device__ float g_asq[NB];
__device__ float g_ent;
__device__ int   g_done;

// ---------------------------------------------------------------------------
// packed f32x2 helpers (Blackwell FFMA2 — 2x fp32 throughput, PTX-only path)
// ---------------------------------------------------------------------------
__device__ __forceinline__ unsigned long long pk2(float lo, float hi){
    unsigned long long r;
    asm("mov.b64 %0, {%1, %2};" : "=l"(r) : "f"(lo), "f"(hi));
    return r;
}
__device__ __forceinline__ void fma2(unsigned long long& d, unsigned long long a, unsigned long long b){
    asm("fma.rn.f32x2 %0, %1, %2, %0;" : "+l"(d) : "l"(a), "l"(b));
}
__device__ __forceinline__ void unpk2(unsigned long long v, float& lo, float& hi){
    asm("mov.b64 {%0, %1}, %2;" : "=f"(lo), "=f"(hi) : "l"(v));
}
// IEEE add/sub the compiler cannot simplify or contract
__device__ __forceinline__ float add_rn(float a, float b){
    float r; asm("add.rn.f32 %0, %1, %2;" : "=f"(r) : "f"(a), "f"(b)); return r;
}
__device__ __forceinline__ float sub_rn(float a, float b){
    float r; asm("sub.rn.f32 %0, %1, %2;" : "=f"(r) : "f"(a), "f"(b)); return r;
}

// ---------------------------------------------------------------------------
// K0: tiny init — zero global accumulators, write constant outputs.
// adj zeroing moved into k_pool (1024 blocks x 64 floats); 'out' fully
// overwritten by k_pool. Grid: 4 blocks x 256.
// ---------------------------------------------------------------------------
__global__ void k_init(float* __restrict__ dout){
    int i = blockIdx.x*256 + threadIdx.x;    // 0..1023
    g_counts[i] = 0.0f;
    if (i < NB){ g_cross[i] = 0.0f; g_asq[i] = 0.0f; }
    if (i == 0){ g_ent = 0.0f; g_done = 0; }
    dout[OFF_BATCH + i] = (float)(i >> 6);   // batch (1024)
    if (i < 17) dout[OFF_PTR + i] = (float)(i << 6);   // batch_ptr_out
}

// ---------------------------------------------------------------------------
// K1: logits GEMM (fp32, f32x2-packed) + gumbel argmax + counts + entropy + c[]
// EXACT R13 form (proven 63.7us, rel_err bit-stable at 9.3474e-4).
// ---------------------------------------------------------------------------
#define WROW 68   // padded smem row stride for W (17 float4)
#define ZROW 65   // padded smem row stride for zs

// float offsets into dynamic smem
#define SM_XS  0            // [128 n][16 f4] = 8192 floats (row-major, swizzled)
#define SM_WS  8192         // [64][WROW] = 4352 floats (per-chunk W)
#define SM_ZS  0            // ALIAS [128 n][ZROW] = 8320 floats (epilogue)
#define SM_BS  12544        // [64]
#define SM_MXS 12608        // [128]
#define SM_CS  12736        // [128] ints
#define SM_TOT 12864        // floats => 51456 B

__global__ void __launch_bounds__(128, 4)
k_assign(const float* __restrict__ x, const float* __restrict__ W,
         const float* __restrict__ bias, const float* __restrict__ gu)
{
    extern __shared__ float sm[];
    float4* xs4 = (float4*)(sm + SM_XS);
    float*  zs  = sm + SM_ZS;
    float*  Ws  = sm + SM_WS;
    float*  bs  = sm + SM_BS;
    float*  mxs = sm + SM_MXS;
    int*    cs  = (int*)(sm + SM_CS);

    const int t     = threadIdx.x;
    const int node0 = blockIdx.x * 128;
    const int gb    = node0 >> 12;      // graph id (4096 nodes per graph)

    if (t < 64) bs[t] = bias[t];

    const int txk = t & 7, tyn = t >> 3;
    const int k0 = txk << 3, m0 = tyn << 3;
    const int swz = tyn & 3;            // x swizzle for this thread's nodes

    unsigned long long acc[8][4];
    #pragma unroll
    for (int i=0;i<8;i++)
        #pragma unroll
        for (int j=0;j<4;j++) acc[i][j] = 0ULL;

    const float4* x4 = (const float4*)x;
    const float4* W4 = (const float4*)W;
    const float4* Ws4 = (const float4*)Ws;

    // ---- two kd chunks of 64; ascending kd order preserved exactly ----
    #pragma unroll 1
    for (int c = 0; c < 2; c++){
        __syncthreads();   // xs/Ws free (prev chunk consumed)

        // stage W rows [c*64, c*64+64) : 1024 float4
        #pragma unroll
        for (int it = 0; it < 8; it++){
            int f = it*128 + t;
            float4 v = W4[c*1024 + f];
            int kd = f >> 4, kq = (f & 15) << 2;
            float* p = Ws + kd*WROW + kq;
            p[0]=v.x; p[1]=v.y; p[2]=v.z; p[3]=v.w;
        }
        // stage x row-major, swizzled: COALESCED LDG (256B per node)
        #pragma unroll
        for (int it = 0; it < 16; it++){
            int f = it*128 + t;
            int n = f >> 4, q = f & 15;
            float4 v = x4[(size_t)(node0 + n)*32 + c*16 + q];
            xs4[n*16 + (q ^ ((n>>3)&3))] = v;
        }
        __syncthreads();

        #pragma unroll 4
        for (int g = 0; g < 16; g++){
            // this thread's 8 node-float4s for kd group g (conflict-free)
            float4 xv[8];
            #pragma unroll
            for (int i=0;i<8;i++)
                xv[i] = xs4[(m0+i)*16 + (g ^ swz)];
            #pragma unroll
            for (int r = 0; r < 4; r++){         // kd = c*64 + 4g + r, ascending
                const float4* wp = Ws4 + (4*g + r)*17 + 2*txk;
                float4 w0 = wp[0], w1 = wp[1];
                unsigned long long rw0 = pk2(w0.x,w0.y), rw1 = pk2(w0.z,w0.w);
                unsigned long long rw2 = pk2(w1.x,w1.y), rw3 = pk2(w1.z,w1.w);
                #pragma unroll
                for (int i=0;i<8;i++){
                    float xr = (r==0) ? xv[i].x : (r==1) ? xv[i].y :
                               (r==2) ? xv[i].z : xv[i].w;
                    unsigned long long xd = pk2(xr, xr);
                    fma2(acc[i][0], xd, rw0);
                    fma2(acc[i][1], xd, rw1);
                    fma2(acc[i][2], xd, rw2);
                    fma2(acc[i][3], xd, rw3);
                }
            }
        }
    }

    // xs/Ws no longer needed; zs reuses the storage
    __syncthreads();

    // ---- per-node: +bias, +gumbel, argmax over 8-lane group; stash z ----
    const float4* u4 = (const float4*)gu;
    #pragma unroll
    for (int i=0;i<8;i++){
        float z[8];
        #pragma unroll
        for (int j=0;j<4;j++){
            float lo, hi; unpk2(acc[i][j], lo, hi);
            z[2*j]   = add_rn(lo, bs[k0 + 2*j]);
            z[2*j+1] = add_rn(hi, bs[k0 + 2*j+1]);
        }
        int node = node0 + m0 + i;
        float4 u0 = u4[(size_t)node*16 + (k0>>2)];
        float4 u1 = u4[(size_t)node*16 + (k0>>2) + 1];
        float uu[8] = {u0.x,u0.y,u0.z,u0.w,u1.x,u1.y,u1.z,u1.w};
        #pragma unroll
        for (int j=0;j<8;j++){
            float g = -(logf)(-(logf)(uu[j]));   // accurate libdevice logf
            z[j] = add_rn(z[j], g);
        }

        // stash exact z for the bit-exact softmax-sum phase
        #pragma unroll
        for (int j=0;j<8;j++) zs[(m0+i)*ZROW + k0 + j] = z[j];

        // local argmax (first-max tie-break, like jnp.argmax)
        float mx = z[0]; int am = k0;
        #pragma unroll
        for (int j=1;j<8;j++) if (z[j] > mx){ mx = z[j]; am = k0+j; }
        // reduce across the 8 lanes holding this node's 64 logits
        #pragma unroll
        for (int off=1; off<8; off<<=1){
            float om = __shfl_xor_sync(0xffffffffu, mx, off);
            int   oa = __shfl_xor_sync(0xffffffffu, am, off);
            if (om > mx || (om == mx && oa < am)){ mx = om; am = oa; }
        }
        if (txk == 0){
            cs[m0+i]  = am;
            mxs[m0+i] = mx;
            atomicAdd(&g_counts[gb*64 + am], 1.0f);
        }
    }
    __syncthreads();
    g_c[node0 + t] = cs[t];

    // ---- phase 2: entropy; SEQUENTIAL ASCENDING softmax denominator ----
    {
        const int lane = t & 31;
        const float* zr = zs + t*ZROW;
        float m  = mxs[t];
        float se = (expf)(sub_rn(zr[0], m));
        #pragma unroll 8
        for (int j = 1; j < 64; j++)
            se = add_rn(se, (expf)(sub_rn(zr[j], m)));
        float ys = __fdiv_rn(1.0f, se);           // y_soft at the argmax
        float sh = sub_rn(add_rn(1.0f, ys), ys);  // straight-through fwd value
        float entloc = -sh * (logf)(sh + 1e-15f);
        #pragma unroll
        for (int off = 16; off; off >>= 1)
            entloc += __shfl_down_sync(0xffffffffu, entloc, off);
        if (lane == 0) atomicAdd(&g_ent, entloc);
    }
}

// ---------------------------------------------------------------------------
// K2: pooling [R13 proven 128t form] + distributed adj zeroing (64 floats per
// block; completes before k_edges by kernel ordering).
// ---------------------------------------------------------------------------
__global__ void __launch_bounds__(128)
k_pool(const float* __restrict__ x, float* __restrict__ dout)
{
    __shared__ int list[NPG];
    __shared__ int wcnt[4];
    const int blk = blockIdx.x;
    const int b = blk >> 6, k = blk & 63;
    const int base = b * NPG;
    const int t = threadIdx.x;
    const int lane = t & 31, w = t >> 5;

    // zero this block's 64-float slice of adj (16 threads x float4)
    if (t < 16)
        ((float4*)(dout + OFF_ADJ))[blk*16 + t] = make_float4(0.f,0.f,0.f,0.f);

    int cv[32];
    #pragma unroll
    for (int i = 0; i < 32; i++)
        cv[i] = g_c[base + w*1024 + i*32 + lane];

    unsigned masks[32];
    int cnt_w = 0;
    #pragma unroll
    for (int i = 0; i < 32; i++){
        unsigned m = __ballot_sync(0xffffffffu, cv[i] == k);
        masks[i] = m;
        cnt_w += __popc(m);
    }
    if (lane == 0) wcnt[w] = cnt_w;
    __syncthreads();

    int off = 0;
    #pragma unroll
    for (int i = 0; i < 4; i++) if (i < w) off += wcnt[i];
    #pragma unroll
    for (int i = 0; i < 32; i++){
        unsigned m = masks[i];
        if (cv[i] == k) list[off + __popc(m & ((1u<<lane)-1u))] = w*1024 + i*32 + lane;
        off += __popc(m);
    }
    __syncthreads();

    const int M = wcnt[0] + wcnt[1] + wcnt[2] + wcnt[3];
    float a0=0.f, a1=0.f, a2=0.f, a3=0.f;
    int idx = 0;
    for (; idx + 4 <= M; idx += 4){
        a0 += x[(size_t)(base + list[idx  ])*128 + t];
        a1 += x[(size_t)(base + list[idx+1])*128 + t];
        a2 += x[(size_t)(base + list[idx+2])*128 + t];
        a3 += x[(size_t)(base + list[idx+3])*128 + t];
    }
    for (; idx < M; idx++) a0 += x[(size_t)(base + list[idx])*128 + t];
    dout[(size_t)blk*128 + t] = (a0+a1)+(a2+a3);
}

// ---------------------------------------------------------------------------
// K3: edges -> out_adj via SMEM histogram; LAST block computes the losses
// (R12-proven fused-fin form: 13.8us vs 10.5+7.6 split).
// ---------------------------------------------------------------------------
#define EPB 2048   // edges per block (32 blocks per graph)
#define ETH 512    // threads per block
#define NBLK (E_TOT/EPB)

__global__ void __launch_bounds__(ETH)
k_edges(const int* __restrict__ ei, const float* __restrict__ ew,
        float* __restrict__ dout)
{
    __shared__ float hist[KC*KC];       // 4096 floats = 16KB
    __shared__ float s_w2[ETH/32], s_cw[ETH/32];
    __shared__ int   s_rank;

    float* adj = dout + OFF_ADJ;
    const int blk = blockIdx.x;         // 512 blocks
    const int b   = blk >> 5;           // graph id (32 blocks per graph)
    const int e0  = blk * EPB;
    const int t   = threadIdx.x;
    const int lane = t & 31, warp = t >> 5;

    // zero histogram
    float4* h4 = (float4*)hist;
    #pragma unroll
    for (int i = 0; i < KC*KC/4/ETH; i++)
        h4[i*ETH + t] = make_float4(0.f,0.f,0.f,0.f);
    __syncthreads();

    float w2 = 0.0f, cw = 0.0f;
    #pragma unroll
    for (int i = 0; i < EPB/ETH; i++){
        int e = e0 + i*ETH + t;
        int s = ei[e], d = ei[E_TOT + e];
        float w = ew[e];
        int cs_ = g_c[s], cd = g_c[d];   // L1-resident (16KB/graph window)
        atomicAdd(&hist[(cs_<<6) + cd], w);
        w2 += w*w;
        if (cs_ == cd) cw += w;
    }

    // block-reduce w2 / cw
    #pragma unroll
    for (int off=16; off; off>>=1){
        w2 += __shfl_down_sync(0xffffffffu, w2, off);
        cw += __shfl_down_sync(0xffffffffu, cw, off);
    }
    if (lane == 0){ s_w2[warp] = w2; s_cw[warp] = cw; }
    __syncthreads();
    if (t == 0){
        float tw2 = 0.f, tcw = 0.f;
        #pragma unroll
        for (int i=0;i<ETH/32;i++){ tw2 += s_w2[i]; tcw += s_cw[i]; }
        atomicAdd(&g_asq[b],   tw2);
        atomicAdd(&g_cross[b], tcw);
        __threadfence();
        s_rank = atomicAdd(&g_done, 1);
    }

    // merge histogram into adj (coalesced REDG; skip empty bins)
    float* adjb = adj + ((size_t)b << 12);
    #pragma unroll
    for (int i = 0; i < KC*KC/ETH; i++){
        int idx = i*ETH + t;
        float v = hist[idx];
        if (v != 0.0f) atomicAdd(&adjb[idx], v);
    }

    __syncthreads();
    // last block computes the losses (identical math to the old k_fin)
    if (s_rank == NBLK - 1 && t < 32){
        __threadfence();
        float link = 0.0f;
        if (t < NB){
            float sst = 0.0f;
            #pragma unroll
            for (int k=0;k<KC;k++){ float c = g_counts[t*KC+k]; sst += c*c; }
            float v = g_asq[t] - 2.0f*g_cross[t] + sst;
            link = sqrtf(fmaxf(v, 0.0f)) * (1.0f/65536.0f);   // / e_per
        }
        #pragma unroll
        for (int off=16; off; off>>=1) link += __shfl_down_sync(0xffffffffu, link, off);
        if (t == 0){
            dout[OFF_LINK] = link * (1.0f/16.0f);
            dout[OFF_ENT]  = g_ent * (1.0f/65536.0f);
        }
    }
}

// ---------------------------------------------------------------------------
extern "C" void kernel_launch(void* const* d_in, const int* in_sizes, int n_in,
                              void* d_out, int out_size)
{
    const float* x  = (const float*)d_in[0];
    const float* W  = (const float*)d_in[1];
    const float* b  = (const float*)d_in[2];
    const float* ew = (const float*)d_in[3];
    const float* gu = (const float*)d_in[4];
    const int*   ei = (const int*)d_in[5];
    // d_in[6] = batch_ptr (int64) — graphs are equal-sized, unused
    float* dout = (float*)d_out;

    const int smem = SM_TOT*4;   // 51456 B -> 4 blocks/SM
    cudaFuncSetAttribute(k_assign, cudaFuncAttributeMaxDynamicSharedMemorySize, smem);

    k_init  <<<4, 256>>>(dout);
    k_assign<<<NTOT/128, 128, smem>>>(x, W, b, gu);
    k_pool  <<<NB*KC, 128>>>(x, dout);
    k_edges <<<NBLK, ETH>>>(ei, ew, dout);
}